// round 10
// baseline (speedup 1.0000x reference)
#include <cuda_runtime.h>

#define DDIM 64
#define NREL 31
#define NE_MAX 100000

// ---- scratch (__device__ globals; allocation-free) ----
__device__ float g_sq[NE_MAX * NREL];   // per-(entity, relation) squared norm
__device__ float g_s[NE_MAX];           // per-entity softmax denominator

// ---------------------------------------------------------------------------
// Zero output (float4) + g_s in one launch.
__global__ void k_zero(float4* out4, int n4, int n_ent) {
    int i = blockIdx.x * blockDim.x + threadIdx.x;
    int stride = gridDim.x * blockDim.x;
    for (int j = i; j < n4; j += stride)
        out4[j] = make_float4(0.f, 0.f, 0.f, 0.f);
    for (int j = i; j < n_ent; j += stride)
        g_s[j] = 0.f;
}

// ---------------------------------------------------------------------------
// g_sq[v, r] = sum_d emb[v,d]^2 * w[r,d]^2   (warp per entity)
__global__ void k_entity_sq(const float* __restrict__ emb,
                            const float* __restrict__ weight, int n_ent) {
    __shared__ float2 w2[NREL * 32];
    for (int i = threadIdx.x; i < NREL * 32; i += blockDim.x) {
        float a = weight[2 * i], b = weight[2 * i + 1];
        w2[i] = make_float2(a * a, b * b);
    }
    __syncthreads();
    int warp = (blockIdx.x * blockDim.x + threadIdx.x) >> 5;
    int lane = threadIdx.x & 31;
    if (warp >= n_ent) return;
    float2 e = reinterpret_cast<const float2*>(emb)[warp * 32 + lane];
    float e0 = e.x * e.x, e1 = e.y * e.y;
    #pragma unroll 4
    for (int r = 0; r < NREL; r++) {
        float2 w = w2[r * 32 + lane];
        float p = e0 * w.x + e1 * w.y;
        #pragma unroll
        for (int o = 16; o; o >>= 1) p += __shfl_xor_sync(0xffffffffu, p, o);
        if (lane == 0) g_sq[warp * NREL + r] = p;
    }
}

// ---------------------------------------------------------------------------
// Fused edge work: groups [0, n_edges) do attention scatter,
// groups [n_edges, n_edges+nnz) do SpMM scatter. 16 lanes per group,
// one float4 RED each. Base lane loads indices / computes exp, broadcasts.
__global__ void k_edge(const float* __restrict__ emb,
                       const float* __restrict__ weight,
                       const int* __restrict__ head,
                       const int* __restrict__ tail,
                       const int* __restrict__ etype, int n_edges,
                       const int* __restrict__ irow,
                       const int* __restrict__ icol,
                       const float* __restrict__ ival, int nnz,
                       float* __restrict__ out,
                       float* __restrict__ out_user) {
    int gid = blockIdx.x * blockDim.x + threadIdx.x;
    int group = gid >> 4;
    int q = threadIdx.x & 15;
    int lane = threadIdx.x & 31;
    int base = lane & 16;                       // 0 or 16: group leader lane
    unsigned mask = 0xFFFFu << base;            // this half-warp only

    if (group < n_edges) {
        int h = 0, t = 0, r = 0;
        float ex = 0.f;
        if (lane == base) {
            h = head[group];
            t = tail[group];
            r = etype[group] - 1;
            ex = __expf(g_sq[h * NREL + r] * g_sq[t * NREL + r]);
        }
        h  = __shfl_sync(mask, h,  base);
        t  = __shfl_sync(mask, t,  base);
        r  = __shfl_sync(mask, r,  base);
        ex = __shfl_sync(mask, ex, base);
        float4 tv = reinterpret_cast<const float4*>(emb + t * DDIM)[q];
        float4 wv = reinterpret_cast<const float4*>(weight + r * DDIM)[q];
        float4 v = make_float4(ex * tv.x * wv.x, ex * tv.y * wv.y,
                               ex * tv.z * wv.z, ex * tv.w * wv.w);
        atomicAdd(reinterpret_cast<float4*>(out + h * DDIM) + q, v);
        if (lane == base) atomicAdd(&g_s[h], ex);
    } else {
        int j = group - n_edges;
        if (j >= nnz) return;
        int rr = 0, c = 0;
        float v = 0.f;
        if (lane == base) {
            rr = irow[j];
            c  = icol[j];
            v  = ival[j];
        }
        rr = __shfl_sync(mask, rr, base);
        c  = __shfl_sync(mask, c,  base);
        v  = __shfl_sync(mask, v,  base);
        float4 ev = reinterpret_cast<const float4*>(emb + c * DDIM)[q];
        float4 av = make_float4(v * ev.x, v * ev.y, v * ev.z, v * ev.w);
        atomicAdd(reinterpret_cast<float4*>(out_user + rr * DDIM) + q, av);
    }
}

// ---------------------------------------------------------------------------
// Fused finish: blocks [0, nb_ent) normalize entity rows by g_s;
// remaining blocks run the per-user softmax-projection epilogue.
__global__ void k_finish(const float* __restrict__ user_emb,
                         const float* __restrict__ weight,
                         float* __restrict__ out,
                         float* __restrict__ out_user,
                         int n_ent, int n_usr, int nb_ent) {
    if ((int)blockIdx.x < nb_ent) {
        int i = blockIdx.x * blockDim.x + threadIdx.x;
        if (i >= n_ent * 16) return;
        int h = i >> 4;
        float s = g_s[h];
        float inv = (s > 0.f) ? 1.f / s : 0.f;
        float4* p = reinterpret_cast<float4*>(out) + i;
        float4 v = *p;
        *p = make_float4(v.x * inv, v.y * inv, v.z * inv, v.w * inv);
    } else {
        __shared__ float2 sw[NREL * 32];
        for (int i = threadIdx.x; i < NREL * 32; i += blockDim.x)
            sw[i] = reinterpret_cast<const float2*>(weight)[i];
        __syncthreads();                       // block-uniform branch: legal
        int u = ((blockIdx.x - nb_ent) * blockDim.x + threadIdx.x) >> 5;
        int lane = threadIdx.x & 31;
        if (u >= n_usr) return;
        float2 ue = reinterpret_cast<const float2*>(user_emb)[u * 32 + lane];
        float myLogit = 0.0f;
        for (int r = 0; r < NREL; r++) {
            float2 w = sw[r * 32 + lane];
            float p = ue.x * w.x + ue.y * w.y;
            #pragma unroll
            for (int o = 16; o; o >>= 1) p += __shfl_xor_sync(0xffffffffu, p, o);
            if (lane == r) myLogit = p;
        }
        float v = (lane < NREL) ? myLogit : -3.4e38f;
        float mx = v;
        #pragma unroll
        for (int o = 16; o; o >>= 1) mx = fmaxf(mx, __shfl_xor_sync(0xffffffffu, mx, o));
        float ex = (lane < NREL) ? __expf(myLogit - mx) : 0.0f;
        float sum = ex;
        #pragma unroll
        for (int o = 16; o; o >>= 1) sum += __shfl_xor_sync(0xffffffffu, sum, o);
        float score = ex / sum;
        float prx = 0.0f, pry = 0.0f;
        for (int r = 0; r < NREL; r++) {
            float sr = __shfl_sync(0xffffffffu, score, r);
            float2 w = sw[r * 32 + lane];
            prx += sr * w.x;
            pry += sr * w.y;
        }
        float2* uo = reinterpret_cast<float2*>(out_user) + u * 32 + lane;
        float2 ua = *uo;
        *uo = make_float2(ua.x + prx * ua.x, ua.y + pry * ua.y);
    }
}

// ---------------------------------------------------------------------------
extern "C" void kernel_launch(void* const* d_in, const int* in_sizes, int n_in,
                              void* d_out, int out_size) {
    const float* entity_emb = (const float*)d_in[0];
    const float* user_emb   = (const float*)d_in[1];
    const int*   edge_index = (const int*)d_in[2];
    const int*   edge_type  = (const int*)d_in[3];
    const int*   irow       = (const int*)d_in[4];
    const int*   icol       = (const int*)d_in[5];
    const float* ival       = (const float*)d_in[6];
    const float* weight     = (const float*)d_in[7];

    int n_ent   = in_sizes[0] / DDIM;
    int n_usr   = in_sizes[1] / DDIM;
    int n_edges = in_sizes[3];
    int nnz     = in_sizes[6];

    float* out      = (float*)d_out;
    float* out_user = out + (long long)n_ent * DDIM;

    const int* head = edge_index;
    const int* tail = edge_index + n_edges;

    int n4 = out_size / 4;
    int nbz = (n4 + 255) / 256; if (nbz > 2048) nbz = 2048;
    k_zero<<<nbz, 256>>>((float4*)out, n4, n_ent);
    k_entity_sq<<<(n_ent * 32 + 255) / 256, 256>>>(entity_emb, weight, n_ent);

    long long tot_threads = (long long)(n_edges + nnz) * 16;
    int nb_edge = (int)((tot_threads + 255) / 256);
    k_edge<<<nb_edge, 256>>>(entity_emb, weight, head, tail, edge_type,
                             n_edges, irow, icol, ival, nnz, out, out_user);

    int nb_ent = (n_ent * 16 + 255) / 256;
    int nb_usr = (n_usr * 32 + 255) / 256;
    k_finish<<<nb_ent + nb_usr, 256>>>(user_emb, weight, out, out_user,
                                       n_ent, n_usr, nb_ent);
}

// round 11
// speedup vs baseline: 1.5421x; 1.5421x over previous
#include <cuda_runtime.h>

#define DDIM 64
#define NREL 31
#define NE_MAX 100000

// ---- scratch (__device__ globals; allocation-free) ----
__device__ float g_sq[NE_MAX * NREL];   // per-(entity, relation) squared norm
__device__ float g_s[NE_MAX];           // per-entity softmax denominator

// ---------------------------------------------------------------------------
// Zero output (float4) + g_s in one launch.
__global__ void k_zero(float4* out4, int n4, int n_ent) {
    int i = blockIdx.x * blockDim.x + threadIdx.x;
    int stride = gridDim.x * blockDim.x;
    for (int j = i; j < n4; j += stride)
        out4[j] = make_float4(0.f, 0.f, 0.f, 0.f);
    for (int j = i; j < n_ent; j += stride)
        g_s[j] = 0.f;
}

// ---------------------------------------------------------------------------
// g_sq[v, r] = sum_d emb[v,d]^2 * w[r,d]^2   (warp per entity)
__global__ void k_entity_sq(const float* __restrict__ emb,
                            const float* __restrict__ weight, int n_ent) {
    __shared__ float2 w2[NREL * 32];
    for (int i = threadIdx.x; i < NREL * 32; i += blockDim.x) {
        float a = weight[2 * i], b = weight[2 * i + 1];
        w2[i] = make_float2(a * a, b * b);
    }
    __syncthreads();
    int warp = (blockIdx.x * blockDim.x + threadIdx.x) >> 5;
    int lane = threadIdx.x & 31;
    if (warp >= n_ent) return;
    float2 e = reinterpret_cast<const float2*>(emb)[warp * 32 + lane];
    float e0 = e.x * e.x, e1 = e.y * e.y;
    #pragma unroll 4
    for (int r = 0; r < NREL; r++) {
        float2 w = w2[r * 32 + lane];
        float p = e0 * w.x + e1 * w.y;
        #pragma unroll
        for (int o = 16; o; o >>= 1) p += __shfl_xor_sync(0xffffffffu, p, o);
        if (lane == 0) g_sq[warp * NREL + r] = p;
    }
}

// ---------------------------------------------------------------------------
// Fused edge work: groups [0, n_edges) do attention scatter,
// groups [n_edges, n_edges+nnz) do SpMM scatter. 16 lanes per group.
// ALL lanes load the small per-edge scalars (L1 broadcast -> high MLP);
// only the leader lane computes expf, broadcast at the last moment.
__global__ void k_edge(const float* __restrict__ emb,
                       const float* __restrict__ weight,
                       const int* __restrict__ head,
                       const int* __restrict__ tail,
                       const int* __restrict__ etype, int n_edges,
                       const int* __restrict__ irow,
                       const int* __restrict__ icol,
                       const float* __restrict__ ival, int nnz,
                       float* __restrict__ out,
                       float* __restrict__ out_user) {
    int gid = blockIdx.x * blockDim.x + threadIdx.x;
    int group = gid >> 4;
    int q = threadIdx.x & 15;
    int lane = threadIdx.x & 31;
    int base = lane & 16;                       // 0 or 16: group leader lane
    unsigned mask = 0xFFFFu << base;            // this half-warp only

    if (group < n_edges) {
        int h = head[group];                    // broadcast loads (all lanes)
        int t = tail[group];
        int r = etype[group] - 1;
        float4 tv = reinterpret_cast<const float4*>(emb + t * DDIM)[q];
        float4 wv = reinterpret_cast<const float4*>(weight + r * DDIM)[q];
        float ex = 0.f;
        if (lane == base)
            ex = __expf(g_sq[h * NREL + r] * g_sq[t * NREL + r]);
        ex = __shfl_sync(mask, ex, base);
        float4 v = make_float4(ex * tv.x * wv.x, ex * tv.y * wv.y,
                               ex * tv.z * wv.z, ex * tv.w * wv.w);
        atomicAdd(reinterpret_cast<float4*>(out + h * DDIM) + q, v);
        if (lane == base) atomicAdd(&g_s[h], ex);
    } else {
        int j = group - n_edges;
        if (j >= nnz) return;
        int rr = irow[j];
        int c  = icol[j];
        float v = ival[j];
        float4 ev = reinterpret_cast<const float4*>(emb + c * DDIM)[q];
        float4 av = make_float4(v * ev.x, v * ev.y, v * ev.z, v * ev.w);
        atomicAdd(reinterpret_cast<float4*>(out_user + rr * DDIM) + q, av);
    }
}

// ---------------------------------------------------------------------------
// Fused finish. Blocks [0, nb_ent): normalize entity rows by g_s
// (thread = one float4). Blocks [nb_ent, ...): per-THREAD user epilogue —
// thread u computes 31 logits from SMEM W (uniform/broadcast LDS.128),
// softmax in registers, projection, fused multiply-add into out_user.
__global__ void k_finish(const float* __restrict__ user_emb,
                         const float* __restrict__ weight,
                         float* __restrict__ out,
                         float* __restrict__ out_user,
                         int n_ent, int n_usr, int nb_ent) {
    if ((int)blockIdx.x < nb_ent) {
        int i = blockIdx.x * blockDim.x + threadIdx.x;
        if (i >= n_ent * 16) return;
        int h = i >> 4;
        float s = g_s[h];
        float inv = (s > 0.f) ? 1.f / s : 0.f;
        float4* p = reinterpret_cast<float4*>(out) + i;
        float4 v = *p;
        *p = make_float4(v.x * inv, v.y * inv, v.z * inv, v.w * inv);
        return;
    }

    __shared__ float4 sw4[NREL][DDIM / 4];      // 31 x 16 float4 = 7936 B
    for (int i = threadIdx.x; i < NREL * (DDIM / 4); i += blockDim.x)
        sw4[i / (DDIM / 4)][i % (DDIM / 4)] =
            reinterpret_cast<const float4*>(weight)[i];
    __syncthreads();                            // block-uniform branch: legal

    int u = (blockIdx.x - nb_ent) * blockDim.x + threadIdx.x;
    if (u >= n_usr) return;

    const float4* ue4 = reinterpret_cast<const float4*>(user_emb) + u * (DDIM / 4);
    float logit[NREL];
    #pragma unroll
    for (int r = 0; r < NREL; r++) logit[r] = 0.f;

    #pragma unroll 4
    for (int dc = 0; dc < DDIM / 4; dc++) {
        float4 e = ue4[dc];
        #pragma unroll
        for (int r = 0; r < NREL; r++) {
            float4 w = sw4[r][dc];
            logit[r] += e.x * w.x + e.y * w.y + e.z * w.z + e.w * w.w;
        }
    }

    float mx = logit[0];
    #pragma unroll
    for (int r = 1; r < NREL; r++) mx = fmaxf(mx, logit[r]);
    float sum = 0.f;
    #pragma unroll
    for (int r = 0; r < NREL; r++) {
        logit[r] = __expf(logit[r] - mx);
        sum += logit[r];
    }
    float inv = 1.f / sum;
    #pragma unroll
    for (int r = 0; r < NREL; r++) logit[r] *= inv;   // now score_r

    float4* uo4 = reinterpret_cast<float4*>(out_user) + u * (DDIM / 4);
    #pragma unroll 4
    for (int dc = 0; dc < DDIM / 4; dc++) {
        float px = 0.f, py = 0.f, pz = 0.f, pw = 0.f;
        #pragma unroll
        for (int r = 0; r < NREL; r++) {
            float4 w = sw4[r][dc];
            float s = logit[r];
            px += s * w.x; py += s * w.y; pz += s * w.z; pw += s * w.w;
        }
        float4 ua = uo4[dc];
        uo4[dc] = make_float4(ua.x + px * ua.x, ua.y + py * ua.y,
                              ua.z + pz * ua.z, ua.w + pw * ua.w);
    }
}

// ---------------------------------------------------------------------------
extern "C" void kernel_launch(void* const* d_in, const int* in_sizes, int n_in,
                              void* d_out, int out_size) {
    const float* entity_emb = (const float*)d_in[0];
    const float* user_emb   = (const float*)d_in[1];
    const int*   edge_index = (const int*)d_in[2];
    const int*   edge_type  = (const int*)d_in[3];
    const int*   irow       = (const int*)d_in[4];
    const int*   icol       = (const int*)d_in[5];
    const float* ival       = (const float*)d_in[6];
    const float* weight     = (const float*)d_in[7];

    int n_ent   = in_sizes[0] / DDIM;
    int n_usr   = in_sizes[1] / DDIM;
    int n_edges = in_sizes[3];
    int nnz     = in_sizes[6];

    float* out      = (float*)d_out;
    float* out_user = out + (long long)n_ent * DDIM;

    const int* head = edge_index;
    const int* tail = edge_index + n_edges;

    int n4 = out_size / 4;
    int nbz = (n4 + 255) / 256; if (nbz > 2048) nbz = 2048;
    k_zero<<<nbz, 256>>>((float4*)out, n4, n_ent);
    k_entity_sq<<<(n_ent * 32 + 255) / 256, 256>>>(entity_emb, weight, n_ent);

    long long tot_threads = (long long)(n_edges + nnz) * 16;
    int nb_edge = (int)((tot_threads + 255) / 256);
    k_edge<<<nb_edge, 256>>>(entity_emb, weight, head, tail, edge_type,
                             n_edges, irow, icol, ival, nnz, out, out_user);

    int nb_ent = (n_ent * 16 + 255) / 256;
    int nb_usr = (n_usr + 255) / 256;
    k_finish<<<nb_ent + nb_usr, 256>>>(user_emb, weight, out, out_user,
                                       n_ent, n_usr, nb_ent);
}